// round 12
// baseline (speedup 1.0000x reference)
#include <cuda_runtime.h>
#include <cuda_bf16.h>
#include <cstdint>

#define NH 16
#define DK 64
#define BATCH 2
#define SEQ 2048
#define DMODEL 1024
#define MROWS (BATCH*SEQ)          // 4096

// Scratch (allocation-free rule: __device__ globals)
__device__ __nv_bfloat16 g_Qh[BATCH*NH*SEQ*DK];
__device__ __nv_bfloat16 g_Ql[BATCH*NH*SEQ*DK];
__device__ __nv_bfloat16 g_Kh[BATCH*NH*SEQ*DK];
__device__ __nv_bfloat16 g_Kl[BATCH*NH*SEQ*DK];
__device__ __nv_bfloat16 g_Vh[BATCH*NH*SEQ*DK];
__device__ __nv_bfloat16 g_Vl[BATCH*NH*SEQ*DK];
__device__ float g_att[MROWS*DMODEL];      // [b,t, h*64+d]

// ============================================================================
// Warp-level MMA + async-copy helpers (sm_80+ portable; works on sm_103)
// ============================================================================
__device__ __forceinline__ uint32_t smem_u32(const void* p) {
    uint32_t a;
    asm("{ .reg .u64 t; cvta.to.shared.u64 t, %1; cvt.u32.u64 %0, t; }"
        : "=r"(a) : "l"(p));
    return a;
}

__device__ __forceinline__ void ldsm_x4(uint32_t* r, uint32_t a) {
    asm volatile("ldmatrix.sync.aligned.m8n8.x4.shared.b16 {%0,%1,%2,%3}, [%4];"
                 : "=r"(r[0]), "=r"(r[1]), "=r"(r[2]), "=r"(r[3]) : "r"(a));
}
__device__ __forceinline__ void ldsm_x4_t(uint32_t* r, uint32_t a) {
    asm volatile("ldmatrix.sync.aligned.m8n8.x4.trans.shared.b16 {%0,%1,%2,%3}, [%4];"
                 : "=r"(r[0]), "=r"(r[1]), "=r"(r[2]), "=r"(r[3]) : "r"(a));
}

__device__ __forceinline__ void mma16816(float* c, const uint32_t* a, const uint32_t* b) {
    asm volatile(
        "mma.sync.aligned.m16n8k16.row.col.f32.bf16.bf16.f32 "
        "{%0,%1,%2,%3}, {%4,%5,%6,%7}, {%8,%9}, {%0,%1,%2,%3};"
        : "+f"(c[0]), "+f"(c[1]), "+f"(c[2]), "+f"(c[3])
        : "r"(a[0]), "r"(a[1]), "r"(a[2]), "r"(a[3]), "r"(b[0]), "r"(b[1]));
}

__device__ __forceinline__ void cp_async16(uint32_t dst, const void* src) {
    asm volatile("cp.async.cg.shared.global [%0], [%1], 16;"
                 :: "r"(dst), "l"(src) : "memory");
}
__device__ __forceinline__ void cp_commit() {
    asm volatile("cp.async.commit_group;" ::: "memory");
}
template<int N> __device__ __forceinline__ void cp_wait() {
    asm volatile("cp.async.wait_group %0;" :: "n"(N) : "memory");
}

// fp32 -> (hi, lo) bf16 split, packed as bf16x2 pairs (element order preserved)
__device__ __forceinline__ void cvt_split4(float4 v, uint2& h, uint2& l) {
    const float h0 = __bfloat162float(__float2bfloat16(v.x));
    const float h1 = __bfloat162float(__float2bfloat16(v.y));
    const float h2 = __bfloat162float(__float2bfloat16(v.z));
    const float h3 = __bfloat162float(__float2bfloat16(v.w));
    __nv_bfloat162 p0 = __floats2bfloat162_rn(h0, h1);
    __nv_bfloat162 p1 = __floats2bfloat162_rn(h2, h3);
    __nv_bfloat162 q0 = __floats2bfloat162_rn(v.x - h0, v.y - h1);
    __nv_bfloat162 q1 = __floats2bfloat162_rn(v.z - h2, v.w - h3);
    h.x = *(uint32_t*)&p0; h.y = *(uint32_t*)&p1;
    l.x = *(uint32_t*)&q0; l.y = *(uint32_t*)&q1;
}

__device__ __forceinline__ void split_pack2(float x, float y, uint32_t& h, uint32_t& l) {
    const float h0 = __bfloat162float(__float2bfloat16(x));
    const float h1 = __bfloat162float(__float2bfloat16(y));
    __nv_bfloat162 hp = __floats2bfloat162_rn(h0, h1);
    __nv_bfloat162 lp = __floats2bfloat162_rn(x - h0, y - h1);
    h = *(uint32_t*)&hp; l = *(uint32_t*)&lp;
}

// ============================================================================
// 3x-bf16-split MMA GEMM (R10/R11-validated).
// ============================================================================
#define A_STRIDE 40    // 32 + 8 pad (bf16 elems)
#define B_STRIDE 136   // 128 + 8 pad

template<bool HEADED>
__device__ __forceinline__ void mma_gemm_body(const float* __restrict__ X,
                                              const float* __restrict__ W,
                                              const float* __restrict__ bias,
                                              float* __restrict__ outF,
                                              __nv_bfloat16* __restrict__ outH,
                                              __nv_bfloat16* __restrict__ outL)
{
    __shared__ __align__(16) __nv_bfloat16 sAhi[128*A_STRIDE];
    __shared__ __align__(16) __nv_bfloat16 sAlo[128*A_STRIDE];
    __shared__ __align__(16) __nv_bfloat16 sBhi[32*B_STRIDE];
    __shared__ __align__(16) __nv_bfloat16 sBlo[32*B_STRIDE];

    const int tid   = threadIdx.x;
    const int wid   = tid >> 5;
    const int lane  = tid & 31;
    const int warpM = wid >> 2;
    const int warpN = wid & 3;
    const int bm = blockIdx.y * 128;
    const int bn = blockIdx.x * 128;

    const int arow  = tid >> 1;
    const int acolB = (tid & 1) * 16;
    const int brow  = tid >> 3;
    const int bcolB = (tid & 7) * 16;

    const uint32_t aHiB = smem_u32(sAhi), aLoB = smem_u32(sAlo);
    const uint32_t bHiB = smem_u32(sBhi), bLoB = smem_u32(sBlo);

    const int aRowL   = warpM*64 + (lane & 15);
    const int aColSel = (lane >> 4) * 8;
    const int bRowL   = (lane & 15);
    const int bColL   = warpN*32 + (lane >> 4) * 8;

    float acc[4][4][4];
    #pragma unroll
    for (int mb = 0; mb < 4; mb++)
        #pragma unroll
        for (int nb = 0; nb < 4; nb++)
            #pragma unroll
            for (int i = 0; i < 4; i++) acc[mb][nb][i] = 0.f;

    float4 avR[4], bvR[4];
    #pragma unroll
    for (int i = 0; i < 4; i++)
        avR[i] = *(const float4*)&X[(long)(bm + arow)*DMODEL + acolB + i*4];
    #pragma unroll
    for (int i = 0; i < 4; i++)
        bvR[i] = *(const float4*)&W[(long)brow*DMODEL + bn + bcolB + i*4];

    for (int kc = 0; kc < 32; kc++) {
        #pragma unroll
        for (int i = 0; i < 4; i++) {
            uint2 h, l; cvt_split4(avR[i], h, l);
            const int off = arow*A_STRIDE + acolB + i*4;
            *(uint2*)&sAhi[off] = h;
            *(uint2*)&sAlo[off] = l;
        }
        #pragma unroll
        for (int i = 0; i < 4; i++) {
            uint2 h, l; cvt_split4(bvR[i], h, l);
            const int off = brow*B_STRIDE + bcolB + i*4;
            *(uint2*)&sBhi[off] = h;
            *(uint2*)&sBlo[off] = l;
        }
        __syncthreads();

        if (kc + 1 < 32) {
            #pragma unroll
            for (int i = 0; i < 4; i++)
                avR[i] = *(const float4*)&X[(long)(bm + arow)*DMODEL + (kc+1)*32 + acolB + i*4];
            #pragma unroll
            for (int i = 0; i < 4; i++)
                bvR[i] = *(const float4*)&W[(long)((kc+1)*32 + brow)*DMODEL + bn + bcolB + i*4];
        }

        #pragma unroll
        for (int ks = 0; ks < 2; ks++) {
            uint32_t aH[4][4], aL[4][4], bH[4][2], bL[4][2];
            #pragma unroll
            for (int mb = 0; mb < 4; mb++) {
                const uint32_t ad =
                    (uint32_t)(((aRowL + mb*16)*A_STRIDE + ks*16 + aColSel) * 2);
                ldsm_x4(aH[mb], aHiB + ad);
                ldsm_x4(aL[mb], aLoB + ad);
            }
            #pragma unroll
            for (int np = 0; np < 2; np++) {
                const uint32_t bd =
                    (uint32_t)(((ks*16 + bRowL)*B_STRIDE + bColL + np*16) * 2);
                uint32_t r[4];
                ldsm_x4_t(r, bHiB + bd);
                bH[np*2][0] = r[0]; bH[np*2][1] = r[1];
                bH[np*2+1][0] = r[2]; bH[np*2+1][1] = r[3];
                ldsm_x4_t(r, bLoB + bd);
                bL[np*2][0] = r[0]; bL[np*2][1] = r[1];
                bL[np*2+1][0] = r[2]; bL[np*2+1][1] = r[3];
            }
            #pragma unroll
            for (int mb = 0; mb < 4; mb++)
                #pragma unroll
                for (int nb = 0; nb < 4; nb++) {
                    mma16816(acc[mb][nb], aH[mb], bH[nb]);
                    mma16816(acc[mb][nb], aH[mb], bL[nb]);
                    mma16816(acc[mb][nb], aL[mb], bH[nb]);
                }
        }
        __syncthreads();
    }

    #pragma unroll
    for (int mb = 0; mb < 4; mb++) {
        #pragma unroll
        for (int nb = 0; nb < 4; nb++) {
            const int m0 = bm + warpM*64 + mb*16 + (lane >> 2);
            const int n  = bn + warpN*32 + nb*8 + (lane & 3)*2;
            const float2 bb2 = *(const float2*)&bias[n];
            const float v0 = acc[mb][nb][0] + bb2.x;
            const float v1 = acc[mb][nb][1] + bb2.y;
            const float v2 = acc[mb][nb][2] + bb2.x;
            const float v3 = acc[mb][nb][3] + bb2.y;
            if (HEADED) {
                const int h = n >> 6, d = n & 63;
                const int b0 = m0 >> 11, t0 = m0 & 2047;
                const long i0 = ((((long)b0*NH + h)*SEQ) + t0)*DK + d;
                uint32_t hh, ll;
                split_pack2(v0, v1, hh, ll);
                *(uint32_t*)&outH[i0] = hh;
                *(uint32_t*)&outL[i0] = ll;
                const int m1 = m0 + 8;
                const int b1 = m1 >> 11, t1 = m1 & 2047;
                const long i1 = ((((long)b1*NH + h)*SEQ) + t1)*DK + d;
                split_pack2(v2, v3, hh, ll);
                *(uint32_t*)&outH[i1] = hh;
                *(uint32_t*)&outL[i1] = ll;
            } else {
                *(float2*)&outF[(long)m0*DMODEL + n] = make_float2(v0, v1);
                *(float2*)&outF[(long)(m0+8)*DMODEL + n] = make_float2(v2, v3);
            }
        }
    }
}

// Merged Q/K/V projection: grid.z selects the projection (one launch, 3x grid)
__global__ __launch_bounds__(256)
void mma_gemm_qkv_all(const float* __restrict__ X,
                      const float* __restrict__ Wq, const float* __restrict__ bq,
                      const float* __restrict__ Wk, const float* __restrict__ bk,
                      const float* __restrict__ Wv, const float* __restrict__ bv)
{
    const int which = blockIdx.z;
    const float* W    = (which == 0) ? Wq : (which == 1) ? Wk : Wv;
    const float* bias = (which == 0) ? bq : (which == 1) ? bk : bv;
    __nv_bfloat16* oh = (which == 0) ? g_Qh : (which == 1) ? g_Kh : g_Vh;
    __nv_bfloat16* ol = (which == 0) ? g_Ql : (which == 1) ? g_Kl : g_Vl;
    mma_gemm_body<true>(X, W, bias, nullptr, oh, ol);
}

__global__ __launch_bounds__(256)
void mma_gemm_out(const float* __restrict__ W, const float* __restrict__ bias,
                  float* __restrict__ out)
{
    mma_gemm_body<false>(g_att, W, bias, out, nullptr, nullptr);
}

// ============================================================================
// Tensor-core flash attention (causal), 3x bf16 split, cp.async double-buffer.
// Block: 64 q rows of one (b,h); 4 warps x 16 rows. Reverse-qt scheduling.
// ============================================================================
#define KV_STRIDE 72                       // 64 + 8 pad (bf16); row pitch 144B
#define ARR_BYTES (64*KV_STRIDE*2)         // 9216 per array
#define BUF_BYTES (4*ARR_BYTES)            // 36864 per buffer (Kh,Kl,Vh,Vl)
#define ATTN_SMEM (2*BUF_BYTES)            // 73728 dynamic

__global__ __launch_bounds__(128)
void attn_mma_kernel()
{
    extern __shared__ __align__(16) char smv[];
    const uint32_t smBase = smem_u32(smv);

    const int tid  = threadIdx.x;
    const int w    = tid >> 5;
    const int lane = tid & 31;
    const int bh   = blockIdx.y;                        // 0..31
    const int qt   = (SEQ/64 - 1) - blockIdx.x;         // heavy blocks first
    const int qbase = qt * 64;
    const int b = bh >> 4, h = bh & 15;

    const long base = (long)bh * SEQ * DK;
    const __nv_bfloat16* garr[4] = { g_Kh + base, g_Kl + base,
                                     g_Vh + base, g_Vl + base };

    // cp.async tile loader: tile kt -> buffer buf (all 128 threads, 16B chunks)
    auto load_tile = [&](int kt, int buf) {
        const long toff = (long)kt * 64 * DK;
        #pragma unroll
        for (int a = 0; a < 4; a++) {
            const __nv_bfloat16* src = garr[a] + toff;
            #pragma unroll
            for (int j = 0; j < 4; j++) {
                const int idx = j*128 + tid;           // 0..511
                const int r = idx >> 3, c = idx & 7;
                cp_async16(smBase + buf*BUF_BYTES + a*ARR_BYTES
                                  + (uint32_t)((r*KV_STRIDE + c*8)*2),
                           src + r*64 + c*8);
            }
        }
    };

    // ---- Prologue: tile 0 -> buf0 (async) while Q stages into buf1 ----
    load_tile(0, 0);
    cp_commit();                                        // group: tile 0
    {
        const uint4* qh4 = (const uint4*)(g_Qh + base + (long)qbase*DK);
        const uint4* ql4 = (const uint4*)(g_Ql + base + (long)qbase*DK);
        for (int i = tid; i < 512; i += 128) {
            const int r = i >> 3, c = i & 7;
            *(uint4*)(smv + BUF_BYTES + (r*KV_STRIDE + c*8)*2) = qh4[i];
            *(uint4*)(smv + BUF_BYTES + ARR_BYTES + (r*KV_STRIDE + c*8)*2) = ql4[i];
        }
    }
    __syncthreads();
    uint32_t qh[4][4], ql[4][4];
    {
        const int rowL = w*16 + (lane & 15);
        const int colSel = (lane >> 4) * 8;
        #pragma unroll
        for (int kb = 0; kb < 4; kb++) {
            const uint32_t ad = (uint32_t)((rowL*KV_STRIDE + kb*16 + colSel) * 2);
            ldsm_x4(qh[kb], smBase + BUF_BYTES + ad);
            ldsm_x4(ql[kb], smBase + BUF_BYTES + ARR_BYTES + ad);
        }
    }
    __syncthreads();    // Q frags read before buf1 is overwritten by tile 1

    float o[8][4];
    #pragma unroll
    for (int nb = 0; nb < 8; nb++)
        #pragma unroll
        for (int i = 0; i < 4; i++) o[nb][i] = 0.f;
    float mA = -1e30f, mB = -1e30f, lA = 0.f, lB = 0.f;

    const int r0 = qbase + w*16 + (lane >> 2);
    const int r1 = r0 + 8;

    const int ntiles = qt + 1;
    for (int kt = 0; kt < ntiles; kt++) {
        const int cur = kt & 1;
        if (kt + 1 < ntiles) load_tile(kt + 1, 1 - cur);
        cp_commit();
        cp_wait<1>();          // tile kt complete (groups retire in order)
        __syncthreads();

        const uint32_t kHiB = smBase + cur*BUF_BYTES;
        const uint32_t kLoB = kHiB + ARR_BYTES;
        const uint32_t vHiB = kHiB + 2*ARR_BYTES;
        const uint32_t vLoB = kHiB + 3*ARR_BYTES;

        // ---- S = Q @ K^T (3-product split) ----
        float s[8][4];
        #pragma unroll
        for (int nb = 0; nb < 8; nb++)
            #pragma unroll
            for (int i = 0; i < 4; i++) s[nb][i] = 0.f;
        {
            const int rA = (lane & 7) + ((lane >> 4) << 3);
            const int cA = ((lane >> 3) & 1) * 8;
            #pragma unroll
            for (int kb = 0; kb < 4; kb++) {
                #pragma unroll
                for (int np = 0; np < 4; np++) {
                    const uint32_t ad =
                        (uint32_t)(((np*16 + rA)*KV_STRIDE + kb*16 + cA) * 2);
                    uint32_t bh4[4], bl4[4];
                    ldsm_x4(bh4, kHiB + ad);
                    ldsm_x4(bl4, kLoB + ad);
                    const uint32_t bHi0[2] = {bh4[0], bh4[1]};
                    const uint32_t bHi1[2] = {bh4[2], bh4[3]};
                    const uint32_t bLo0[2] = {bl4[0], bl4[1]};
                    const uint32_t bLo1[2] = {bl4[2], bl4[3]};
                    mma16816(s[2*np],   qh[kb], bHi0);
                    mma16816(s[2*np],   qh[kb], bLo0);
                    mma16816(s[2*np],   ql[kb], bHi0);
                    mma16816(s[2*np+1], qh[kb], bHi1);
                    mma16816(s[2*np+1], qh[kb], bLo1);
                    mma16816(s[2*np+1], ql[kb], bHi1);
                }
            }
        }

        // ---- Scale + causal mask (diagonal tile only) ----
        const bool diag = (kt == qt);
        #pragma unroll
        for (int nb = 0; nb < 8; nb++) {
            #pragma unroll
            for (int i = 0; i < 4; i++) s[nb][i] *= 0.125f;
            if (diag) {
                const int col = kt*64 + nb*8 + (lane & 3)*2;
                if (col     > r0) s[nb][0] = -1e30f;
                if (col + 1 > r0) s[nb][1] = -1e30f;
                if (col     > r1) s[nb][2] = -1e30f;
                if (col + 1 > r1) s[nb][3] = -1e30f;
            }
        }

        // ---- Online softmax in registers ----
        float rmA = -1e30f, rmB = -1e30f;
        #pragma unroll
        for (int nb = 0; nb < 8; nb++) {
            rmA = fmaxf(rmA, fmaxf(s[nb][0], s[nb][1]));
            rmB = fmaxf(rmB, fmaxf(s[nb][2], s[nb][3]));
        }
        rmA = fmaxf(rmA, __shfl_xor_sync(0xffffffffu, rmA, 1));
        rmA = fmaxf(rmA, __shfl_xor_sync(0xffffffffu, rmA, 2));
        rmB = fmaxf(rmB, __shfl_xor_sync(0xffffffffu, rmB, 1));
        rmB = fmaxf(rmB, __shfl_xor_sync(0xffffffffu, rmB, 2));

        const float mAn = fmaxf(mA, rmA);
        const float mBn = fmaxf(mB, rmB);
        const float cA = __expf(mA - mAn);
        const float cB = __expf(mB - mBn);

        float sumA = 0.f, sumB = 0.f;
        #pragma unroll
        for (int nb = 0; nb < 8; nb++) {
            s[nb][0] = __expf(s[nb][0] - mAn);
            s[nb][1] = __expf(s[nb][1] - mAn);
            s[nb][2] = __expf(s[nb][2] - mBn);
            s[nb][3] = __expf(s[nb][3] - mBn);
            sumA += s[nb][0] + s[nb][1];
            sumB += s[nb][2] + s[nb][3];
        }
        sumA += __shfl_xor_sync(0xffffffffu, sumA, 1);
        sumA += __shfl_xor_sync(0xffffffffu, sumA, 2);
        sumB += __shfl_xor_sync(0xffffffffu, sumB, 1);
        sumB += __shfl_xor_sync(0xffffffffu, sumB, 2);

        lA = lA*cA + sumA;
        lB = lB*cB + sumB;
        mA = mAn; mB = mBn;

        #pragma unroll
        for (int nb = 0; nb < 8; nb++) {
            o[nb][0] *= cA; o[nb][1] *= cA;
            o[nb][2] *= cB; o[nb][3] *= cB;
        }

        // ---- Pack P into A fragments ----
        uint32_t aPh[4][4], aPl[4][4];
        #pragma unroll
        for (int kb = 0; kb < 4; kb++) {
            split_pack2(s[2*kb][0],   s[2*kb][1],   aPh[kb][0], aPl[kb][0]);
            split_pack2(s[2*kb][2],   s[2*kb][3],   aPh[kb][1], aPl[kb][1]);
            split_pack2(s[2*kb+1][0], s[2*kb+1][1], aPh[kb][2], aPl[kb][2]);
            split_pack2(s[2*kb+1][2], s[2*kb+1][3], aPh[kb][3], aPl[kb][3]);
        }

        // ---- O += P @ V (3-product split) ----
        {
            const int rB = lane & 15;
            const int cB2 = (lane >> 4) * 8;
            #pragma unroll
            for (int kb = 0; kb < 4; kb++) {
                #pragma unroll
                for (int np = 0; np < 4; np++) {
                    const uint32_t bd =
                        (uint32_t)(((kb*16 + rB)*KV_STRIDE + np*16 + cB2) * 2);
                    uint32_t vh4[4], vl4[4];
                    ldsm_x4_t(vh4, vHiB + bd);
                    ldsm_x4_t(vl4, vLoB + bd);
                    const uint32_t vHi0[2] = {vh4[0], vh4[1]};
                    const uint32_t vHi1[2] = {vh4[2], vh4[3]};
                    const uint32_t vLo0[2] = {vl4[0], vl4[1]};
                    const uint32_t vLo1[2] = {vl4[2], vl4[3]};
                    mma16816(o[2*np],   aPh[kb], vHi0);
                    mma16816(o[2*np],   aPh[kb], vLo0);
                    mma16816(o[2*np],   aPl[kb], vHi0);
                    mma16816(o[2*np+1], aPh[kb], vHi1);
                    mma16816(o[2*np+1], aPh[kb], vLo1);
                    mma16816(o[2*np+1], aPl[kb], vHi1);
                }
            }
        }
        __syncthreads();   // all warps done with buf[cur] before overwrite
    }

    // ---- Normalize and store to g_att [b,t, h*64+d] ----
    const float invA = 1.f / lA;
    const float invB = 1.f / lB;
    #pragma unroll
    for (int nb = 0; nb < 8; nb++) {
        const int d = nb*8 + (lane & 3)*2;
        float2 v01 = make_float2(o[nb][0]*invA, o[nb][1]*invA);
        float2 v23 = make_float2(o[nb][2]*invB, o[nb][3]*invB);
        *(float2*)&g_att[((long)(b*SEQ + r0))*DMODEL + h*DK + d] = v01;
        *(float2*)&g_att[((long)(b*SEQ + r1))*DMODEL + h*DK + d] = v23;
    }
}

// ---------------------------------------------------------------------------
extern "C" void kernel_launch(void* const* d_in, const int* in_sizes, int n_in,
                              void* d_out, int out_size)
{
    const float* x  = (const float*)d_in[0];
    // d_in[1] = mask (int32 causal tril) — causality applied analytically
    const float* Wq = (const float*)d_in[2];
    const float* bq = (const float*)d_in[3];
    const float* Wk = (const float*)d_in[4];
    const float* bk = (const float*)d_in[5];
    const float* Wv = (const float*)d_in[6];
    const float* bv = (const float*)d_in[7];
    const float* Wo = (const float*)d_in[8];
    const float* bo = (const float*)d_in[9];
    float* out = (float*)d_out;

    // Host-side, idempotent, capture-legal (not a stream op, no allocation)
    cudaFuncSetAttribute(attn_mma_kernel,
                         cudaFuncAttributeMaxDynamicSharedMemorySize, ATTN_SMEM);

    dim3 qkvgrid(DMODEL/128, MROWS/128, 3);   // (8, 32, 3)
    mma_gemm_qkv_all<<<qkvgrid, 256>>>(x, Wq, bq, Wk, bk, Wv, bv);

    dim3 agrid(SEQ/64, BATCH*NH);             // (32, 32)
    attn_mma_kernel<<<agrid, 128, ATTN_SMEM>>>();

    dim3 ogrid(DMODEL/128, MROWS/128);        // (8, 32)
    mma_gemm_out<<<ogrid, 256>>>(Wo, bo, out);
}

// round 15
// speedup vs baseline: 1.0639x; 1.0639x over previous
#include <cuda_runtime.h>
#include <cuda_bf16.h>
#include <cstdint>

#define NH 16
#define DK 64
#define BATCH 2
#define SEQ 2048
#define DMODEL 1024
#define MROWS (BATCH*SEQ)          // 4096

// Scratch (allocation-free rule: __device__ globals)
__device__ __nv_bfloat16 g_Qh[BATCH*NH*SEQ*DK];
__device__ __nv_bfloat16 g_Ql[BATCH*NH*SEQ*DK];
__device__ __nv_bfloat16 g_Kh[BATCH*NH*SEQ*DK];
__device__ __nv_bfloat16 g_Kl[BATCH*NH*SEQ*DK];
__device__ __nv_bfloat16 g_Vh[BATCH*NH*SEQ*DK];
__device__ __nv_bfloat16 g_Vl[BATCH*NH*SEQ*DK];
__device__ float g_att[MROWS*DMODEL];      // [b,t, h*64+d]

// ============================================================================
// Warp-level MMA + async-copy helpers (sm_80+ portable; works on sm_103)
// ============================================================================
__device__ __forceinline__ uint32_t smem_u32(const void* p) {
    uint32_t a;
    asm("{ .reg .u64 t; cvta.to.shared.u64 t, %1; cvt.u32.u64 %0, t; }"
        : "=r"(a) : "l"(p));
    return a;
}

__device__ __forceinline__ void ldsm_x4(uint32_t* r, uint32_t a) {
    asm volatile("ldmatrix.sync.aligned.m8n8.x4.shared.b16 {%0,%1,%2,%3}, [%4];"
                 : "=r"(r[0]), "=r"(r[1]), "=r"(r[2]), "=r"(r[3]) : "r"(a));
}
__device__ __forceinline__ void ldsm_x4_t(uint32_t* r, uint32_t a) {
    asm volatile("ldmatrix.sync.aligned.m8n8.x4.trans.shared.b16 {%0,%1,%2,%3}, [%4];"
                 : "=r"(r[0]), "=r"(r[1]), "=r"(r[2]), "=r"(r[3]) : "r"(a));
}

__device__ __forceinline__ void mma16816(float* c, const uint32_t* a, const uint32_t* b) {
    asm volatile(
        "mma.sync.aligned.m16n8k16.row.col.f32.bf16.bf16.f32 "
        "{%0,%1,%2,%3}, {%4,%5,%6,%7}, {%8,%9}, {%0,%1,%2,%3};"
        : "+f"(c[0]), "+f"(c[1]), "+f"(c[2]), "+f"(c[3])
        : "r"(a[0]), "r"(a[1]), "r"(a[2]), "r"(a[3]), "r"(b[0]), "r"(b[1]));
}

__device__ __forceinline__ void cp_async16(uint32_t dst, const void* src) {
    asm volatile("cp.async.cg.shared.global [%0], [%1], 16;"
                 :: "r"(dst), "l"(src) : "memory");
}
__device__ __forceinline__ void cp_commit() {
    asm volatile("cp.async.commit_group;" ::: "memory");
}
template<int N> __device__ __forceinline__ void cp_wait() {
    asm volatile("cp.async.wait_group %0;" :: "n"(N) : "memory");
}

// fp32 -> (hi, lo) bf16 split, packed as bf16x2 pairs (element order preserved)
__device__ __forceinline__ void cvt_split4(float4 v, uint2& h, uint2& l) {
    const float h0 = __bfloat162float(__float2bfloat16(v.x));
    const float h1 = __bfloat162float(__float2bfloat16(v.y));
    const float h2 = __bfloat162float(__float2bfloat16(v.z));
    const float h3 = __bfloat162float(__float2bfloat16(v.w));
    __nv_bfloat162 p0 = __floats2bfloat162_rn(h0, h1);
    __nv_bfloat162 p1 = __floats2bfloat162_rn(h2, h3);
    __nv_bfloat162 q0 = __floats2bfloat162_rn(v.x - h0, v.y - h1);
    __nv_bfloat162 q1 = __floats2bfloat162_rn(v.z - h2, v.w - h3);
    h.x = *(uint32_t*)&p0; h.y = *(uint32_t*)&p1;
    l.x = *(uint32_t*)&q0; l.y = *(uint32_t*)&q1;
}

__device__ __forceinline__ void split_pack2(float x, float y, uint32_t& h, uint32_t& l) {
    const float h0 = __bfloat162float(__float2bfloat16(x));
    const float h1 = __bfloat162float(__float2bfloat16(y));
    __nv_bfloat162 hp = __floats2bfloat162_rn(h0, h1);
    __nv_bfloat162 lp = __floats2bfloat162_rn(x - h0, y - h1);
    h = *(uint32_t*)&hp; l = *(uint32_t*)&lp;
}

// ============================================================================
// 3x-bf16-split MMA GEMM (R10/R11-validated, inline conversion).
// ============================================================================
#define A_STRIDE 40    // 32 + 8 pad (bf16 elems)
#define B_STRIDE 136   // 128 + 8 pad

template<bool HEADED>
__device__ __forceinline__ void mma_gemm_body(const float* __restrict__ X,
                                              const float* __restrict__ W,
                                              const float* __restrict__ bias,
                                              float* __restrict__ outF,
                                              __nv_bfloat16* __restrict__ outH,
                                              __nv_bfloat16* __restrict__ outL)
{
    __shared__ __align__(16) __nv_bfloat16 sAhi[128*A_STRIDE];
    __shared__ __align__(16) __nv_bfloat16 sAlo[128*A_STRIDE];
    __shared__ __align__(16) __nv_bfloat16 sBhi[32*B_STRIDE];
    __shared__ __align__(16) __nv_bfloat16 sBlo[32*B_STRIDE];

    const int tid   = threadIdx.x;
    const int wid   = tid >> 5;
    const int lane  = tid & 31;
    const int warpM = wid >> 2;
    const int warpN = wid & 3;
    const int bm = blockIdx.y * 128;
    const int bn = blockIdx.x * 128;

    const int arow  = tid >> 1;
    const int acolB = (tid & 1) * 16;
    const int brow  = tid >> 3;
    const int bcolB = (tid & 7) * 16;

    const uint32_t aHiB = smem_u32(sAhi), aLoB = smem_u32(sAlo);
    const uint32_t bHiB = smem_u32(sBhi), bLoB = smem_u32(sBlo);

    const int aRowL   = warpM*64 + (lane & 15);
    const int aColSel = (lane >> 4) * 8;
    const int bRowL   = (lane & 15);
    const int bColL   = warpN*32 + (lane >> 4) * 8;

    float acc[4][4][4];
    #pragma unroll
    for (int mb = 0; mb < 4; mb++)
        #pragma unroll
        for (int nb = 0; nb < 4; nb++)
            #pragma unroll
            for (int i = 0; i < 4; i++) acc[mb][nb][i] = 0.f;

    float4 avR[4], bvR[4];
    #pragma unroll
    for (int i = 0; i < 4; i++)
        avR[i] = *(const float4*)&X[(long)(bm + arow)*DMODEL + acolB + i*4];
    #pragma unroll
    for (int i = 0; i < 4; i++)
        bvR[i] = *(const float4*)&W[(long)brow*DMODEL + bn + bcolB + i*4];

    for (int kc = 0; kc < 32; kc++) {
        #pragma unroll
        for (int i = 0; i < 4; i++) {
            uint2 h, l; cvt_split4(avR[i], h, l);
            const int off = arow*A_STRIDE + acolB + i*4;
            *(uint2*)&sAhi[off] = h;
            *(uint2*)&sAlo[off] = l;
        }
        #pragma unroll
        for (int i = 0; i < 4; i++) {
            uint2 h, l; cvt_split4(bvR[i], h, l);
            const int off = brow*B_STRIDE + bcolB + i*4;
            *(uint2*)&sBhi[off] = h;
            *(uint2*)&sBlo[off] = l;
        }
        __syncthreads();

        if (kc + 1 < 32) {
            #pragma unroll
            for (int i = 0; i < 4; i++)
                avR[i] = *(const float4*)&X[(long)(bm + arow)*DMODEL + (kc+1)*32 + acolB + i*4];
            #pragma unroll
            for (int i = 0; i < 4; i++)
                bvR[i] = *(const float4*)&W[(long)((kc+1)*32 + brow)*DMODEL + bn + bcolB + i*4];
        }

        #pragma unroll
        for (int ks = 0; ks < 2; ks++) {
            uint32_t aH[4][4], aL[4][4], bH[4][2], bL[4][2];
            #pragma unroll
            for (int mb = 0; mb < 4; mb++) {
                const uint32_t ad =
                    (uint32_t)(((aRowL + mb*16)*A_STRIDE + ks*16 + aColSel) * 2);
                ldsm_x4(aH[mb], aHiB + ad);
                ldsm_x4(aL[mb], aLoB + ad);
            }
            #pragma unroll
            for (int np = 0; np < 2; np++) {
                const uint32_t bd =
                    (uint32_t)(((ks*16 + bRowL)*B_STRIDE + bColL + np*16) * 2);
                uint32_t r[4];
                ldsm_x4_t(r, bHiB + bd);
                bH[np*2][0] = r[0]; bH[np*2][1] = r[1];
                bH[np*2+1][0] = r[2]; bH[np*2+1][1] = r[3];
                ldsm_x4_t(r, bLoB + bd);
                bL[np*2][0] = r[0]; bL[np*2][1] = r[1];
                bL[np*2+1][0] = r[2]; bL[np*2+1][1] = r[3];
            }
            #pragma unroll
            for (int mb = 0; mb < 4; mb++)
                #pragma unroll
                for (int nb = 0; nb < 4; nb++) {
                    mma16816(acc[mb][nb], aH[mb], bH[nb]);
                    mma16816(acc[mb][nb], aH[mb], bL[nb]);
                    mma16816(acc[mb][nb], aL[mb], bH[nb]);
                }
        }
        __syncthreads();
    }

    #pragma unroll
    for (int mb = 0; mb < 4; mb++) {
        #pragma unroll
        for (int nb = 0; nb < 4; nb++) {
            const int m0 = bm + warpM*64 + mb*16 + (lane >> 2);
            const int n  = bn + warpN*32 + nb*8 + (lane & 3)*2;
            const float2 bb2 = *(const float2*)&bias[n];
            const float v0 = acc[mb][nb][0] + bb2.x;
            const float v1 = acc[mb][nb][1] + bb2.y;
            const float v2 = acc[mb][nb][2] + bb2.x;
            const float v3 = acc[mb][nb][3] + bb2.y;
            if (HEADED) {
                const int h = n >> 6, d = n & 63;
                const int b0 = m0 >> 11, t0 = m0 & 2047;
                const long i0 = ((((long)b0*NH + h)*SEQ) + t0)*DK + d;
                uint32_t hh, ll;
                split_pack2(v0, v1, hh, ll);
                *(uint32_t*)&outH[i0] = hh;
                *(uint32_t*)&outL[i0] = ll;
                const int m1 = m0 + 8;
                const int b1 = m1 >> 11, t1 = m1 & 2047;
                const long i1 = ((((long)b1*NH + h)*SEQ) + t1)*DK + d;
                split_pack2(v2, v3, hh, ll);
                *(uint32_t*)&outH[i1] = hh;
                *(uint32_t*)&outL[i1] = ll;
            } else {
                *(float2*)&outF[(long)m0*DMODEL + n] = make_float2(v0, v1);
                *(float2*)&outF[(long)(m0+8)*DMODEL + n] = make_float2(v2, v3);
            }
        }
    }
}

// Separate QKV launches (R11 config — measured faster than merged)
__global__ __launch_bounds__(256)
void mma_gemm_qkv(const float* __restrict__ X, const float* __restrict__ W,
                  const float* __restrict__ bias, int which)
{
    __nv_bfloat16* oh = (which == 0) ? g_Qh : (which == 1) ? g_Kh : g_Vh;
    __nv_bfloat16* ol = (which == 0) ? g_Ql : (which == 1) ? g_Kl : g_Vl;
    mma_gemm_body<true>(X, W, bias, nullptr, oh, ol);
}

__global__ __launch_bounds__(256)
void mma_gemm_out(const float* __restrict__ W, const float* __restrict__ bias,
                  float* __restrict__ out)
{
    mma_gemm_body<false>(g_att, W, bias, out, nullptr, nullptr);
}

// ============================================================================
// Tensor-core flash attention (causal), 3x bf16 split, cp.async double-buffer.
// Block: 64 q rows of one (b,h); 4 warps x 16 rows. Reverse-qt scheduling.
// (Byte-identical to the R12 kernel that passed and measured ~175us.)
// ============================================================================
#define KV_STRIDE 72                       // 64 + 8 pad (bf16); row pitch 144B
#define ARR_BYTES (64*KV_STRIDE*2)         // 9216 per array
#define BUF_BYTES (4*ARR_BYTES)            // 36864 per buffer (Kh,Kl,Vh,Vl)
#define ATTN_SMEM (2*BUF_BYTES)            // 73728 dynamic

__global__ __launch_bounds__(128)
void attn_mma_kernel()
{
    extern __shared__ __align__(16) char smv[];
    const uint32_t smBase = smem_u32(smv);

    const int tid  = threadIdx.x;
    const int w    = tid >> 5;
    const int lane = tid & 31;
    const int bh   = blockIdx.y;                        // 0..31
    const int qt   = (SEQ/64 - 1) - blockIdx.x;         // heavy blocks first
    const int qbase = qt * 64;
    const int b = bh >> 4, h = bh & 15;

    const long base = (long)bh * SEQ * DK;
    const __nv_bfloat16* garr[4] = { g_Kh + base, g_Kl + base,
                                     g_Vh + base, g_Vl + base };

    auto load_tile = [&](int kt, int buf) {
        const long toff = (long)kt * 64 * DK;
        #pragma unroll
        for (int a = 0; a < 4; a++) {
            const __nv_bfloat16* src = garr[a] + toff;
            #pragma unroll
            for (int j = 0; j < 4; j++) {
                const int idx = j*128 + tid;           // 0..511
                const int r = idx >> 3, c = idx & 7;
                cp_async16(smBase + buf*BUF_BYTES + a*ARR_BYTES
                                  + (uint32_t)((r*KV_STRIDE + c*8)*2),
                           src + r*64 + c*8);
            }
        }
    };

    // ---- Prologue: tile 0 -> buf0 (async) while Q stages into buf1 ----
    load_tile(0, 0);
    cp_commit();
    {
        const uint4* qh4 = (const uint4*)(g_Qh + base + (long)qbase*DK);
        const uint4* ql4 = (const uint4*)(g_Ql + base + (long)qbase*DK);
        for (int i = tid; i < 512; i += 128) {
            const int r = i >> 3, c = i & 7;
            *(uint4*)(smv + BUF_BYTES + (r*KV_STRIDE + c*8)*2) = qh4[i];
            *(uint4*)(smv + BUF_BYTES + ARR_BYTES + (r*KV_STRIDE + c*8)*2) = ql4[i];
        }
    }
    __syncthreads();
    uint32_t qh[4][4], ql[4][4];
    {
        const int rowL = w*16 + (lane & 15);
        const int colSel = (lane >> 4) * 8;
        #pragma unroll
        for (int kb = 0; kb < 4; kb++) {
            const uint32_t ad = (uint32_t)((rowL*KV_STRIDE + kb*16 + colSel) * 2);
            ldsm_x4(qh[kb], smBase + BUF_BYTES + ad);
            ldsm_x4(ql[kb], smBase + BUF_BYTES + ARR_BYTES + ad);
        }
    }
    __syncthreads();

    float o[8][4];
    #pragma unroll
    for (int nb = 0; nb < 8; nb++)
        #pragma unroll
        for (int i = 0; i < 4; i++) o[nb][i] = 0.f;
    float mA = -1e30f, mB = -1e30f, lA = 0.f, lB = 0.f;

    const int r0 = qbase + w*16 + (lane >> 2);
    const int r1 = r0 + 8;

    const int ntiles = qt + 1;
    for (int kt = 0; kt < ntiles; kt++) {
        const int cur = kt & 1;
        if (kt + 1 < ntiles) load_tile(kt + 1, 1 - cur);
        cp_commit();
        cp_wait<1>();
        __syncthreads();

        const uint32_t kHiB = smBase + cur*BUF_BYTES;
        const uint32_t kLoB = kHiB + ARR_BYTES;
        const uint32_t vHiB = kHiB + 2*ARR_BYTES;
        const uint32_t vLoB = kHiB + 3*ARR_BYTES;

        // ---- S = Q @ K^T (3-product split) ----
        float s[8][4];
        #pragma unroll
        for (int nb = 0; nb < 8; nb++)
            #pragma unroll
            for (int i = 0; i < 4; i++) s[nb][i] = 0.f;
        {
            const int rA = (lane & 7) + ((lane >> 4) << 3);
            const int cA = ((lane >> 3) & 1) * 8;
            #pragma unroll
            for (int kb = 0; kb < 4; kb++) {
                #pragma unroll
                for (int np = 0; np < 4; np++) {
                    const uint32_t ad =
                        (uint32_t)(((np*16 + rA)*KV_STRIDE + kb*16 + cA) * 2);
                    uint32_t bh4[4], bl4[4];
                    ldsm_x4(bh4, kHiB + ad);
                    ldsm_x4(bl4, kLoB + ad);
                    const uint32_t bHi0[2] = {bh4[0], bh4[1]};
                    const uint32_t bHi1[2] = {bh4[2], bh4[3]};
                    const uint32_t bLo0[2] = {bl4[0], bl4[1]};
                    const uint32_t bLo1[2] = {bl4[2], bl4[3]};
                    mma16816(s[2*np],   qh[kb], bHi0);
                    mma16816(s[2*np],   qh[kb], bLo0);
                    mma16816(s[2*np],   ql[kb], bHi0);
                    mma16816(s[2*np+1], qh[kb], bHi1);
                    mma16816(s[2*np+1], qh[kb], bLo1);
                    mma16816(s[2*np+1], ql[kb], bHi1);
                }
            }
        }

        // ---- Scale + causal mask (diagonal tile only) ----
        const bool diag = (kt == qt);
        #pragma unroll
        for (int nb = 0; nb < 8; nb++) {
            #pragma unroll
            for (int i = 0; i < 4; i++) s[nb][i] *= 0.125f;
            if (diag) {
                const int col = kt*64 + nb*8 + (lane & 3)*2;
                if (col     > r0) s[nb][0] = -1e30f;
                if (col + 1 > r0) s[nb][1] = -1e30f;
                if (col     > r1) s[nb][2] = -1e30f;
                if (col + 1 > r1) s[nb][3] = -1e30f;
            }
        }

        // ---- Online softmax in registers ----
        float rmA = -1e30f, rmB = -1e30f;
        #pragma unroll
        for (int nb = 0; nb < 8; nb++) {
            rmA = fmaxf(rmA, fmaxf(s[nb][0], s[nb][1]));
            rmB = fmaxf(rmB, fmaxf(s[nb][2], s[nb][3]));
        }
        rmA = fmaxf(rmA, __shfl_xor_sync(0xffffffffu, rmA, 1));
        rmA = fmaxf(rmA, __shfl_xor_sync(0xffffffffu, rmA, 2));
        rmB = fmaxf(rmB, __shfl_xor_sync(0xffffffffu, rmB, 1));
        rmB = fmaxf(rmB, __shfl_xor_sync(0xffffffffu, rmB, 2));

        const float mAn = fmaxf(mA, rmA);
        const float mBn = fmaxf(mB, rmB);
        const float cA = __expf(mA - mAn);
        const float cB = __expf(mB - mBn);

        float sumA = 0.f, sumB = 0.f;
        #pragma unroll
        for (int nb = 0; nb < 8; nb++) {
            s[nb][0] = __expf(s[nb][0] - mAn);
            s[nb][1] = __expf(s[nb][1] - mAn);
            s[nb][2] = __expf(s[nb][2] - mBn);
            s[nb][3] = __expf(s[nb][3] - mBn);
            sumA += s[nb][0] + s[nb][1];
            sumB += s[nb][2] + s[nb][3];
        }
        sumA += __shfl_xor_sync(0xffffffffu, sumA, 1);
        sumA += __shfl_xor_sync(0xffffffffu, sumA, 2);
        sumB += __shfl_xor_sync(0xffffffffu, sumB, 1);
        sumB += __shfl_xor_sync(0xffffffffu, sumB, 2);

        lA = lA*cA + sumA;
        lB = lB*cB + sumB;
        mA = mAn; mB = mBn;

        #pragma unroll
        for (int nb = 0; nb < 8; nb++) {
            o[nb][0] *= cA; o[nb][1] *= cA;
            o[nb][2] *= cB; o[nb][3] *= cB;
        }

        // ---- Pack P into A fragments ----
        uint32_t aPh[4][4], aPl[4][4];
        #pragma unroll
        for (int kb = 0; kb < 4; kb++) {
            split_pack2(s[2*kb][0],   s[2*kb][1],   aPh[kb][0], aPl[kb][0]);
            split_pack2(s[2*kb][2],   s[2*kb][3],   aPh[kb][1], aPl[kb][1]);
            split_pack2(s[2*kb+1][0], s[2*kb+1][1], aPh[kb][2], aPl[kb][2]);
            split_pack2(s[2*kb+1][2], s[2*kb+1][3], aPh[kb][3], aPl[kb][3]);
        }

        // ---- O += P @ V (3-product split) ----
        {
            const int rB = lane & 15;
            const int cB2 = (lane >> 4) * 8;
            #pragma unroll
            for (int kb = 0; kb < 4; kb++) {
                #pragma unroll
                for (int np = 0; np < 4; np++) {
                    const uint32_t bd =
                        (uint32_t)(((kb*16 + rB)*KV_STRIDE + np*16 + cB2) * 2);
                    uint32_t vh4[4], vl4[4];
                    ldsm_x4_t(vh4, vHiB + bd);
                    ldsm_x4_t(vl4, vLoB + bd);
                    const uint32_t vHi0[2] = {vh4[0], vh4[1]};
                    const uint32_t vHi1[2] = {vh4[2], vh4[3]};
                    const uint32_t vLo0[2] = {vl4[0], vl4[1]};
                    const uint32_t vLo1[2] = {vl4[2], vl4[3]};
                    mma16816(o[2*np],   aPh[kb], vHi0);
                    mma16816(o[2*np],   aPh[kb], vLo0);
                    mma16816(o[2*np],   aPl[kb], vHi0);
                    mma16816(o[2*np+1], aPh[kb], vHi1);
                    mma16816(o[2*np+1], aPh[kb], vLo1);
                    mma16816(o[2*np+1], aPl[kb], vHi1);
                }
            }
        }
        __syncthreads();
    }

    // ---- Normalize and store to g_att [b,t, h*64+d] ----
    const float invA = 1.f / lA;
    const float invB = 1.f / lB;
    #pragma unroll
    for (int nb = 0; nb < 8; nb++) {
        const int d = nb*8 + (lane & 3)*2;
        float2 v01 = make_float2(o[nb][0]*invA, o[nb][1]*invA);
        float2 v23 = make_float2(o[nb][2]*invB, o[nb][3]*invB);
        *(float2*)&g_att[((long)(b*SEQ + r0))*DMODEL + h*DK + d] = v01;
        *(float2*)&g_att[((long)(b*SEQ + r1))*DMODEL + h*DK + d] = v23;
    }
}

// ---------------------------------------------------------------------------
extern "C" void kernel_launch(void* const* d_in, const int* in_sizes, int n_in,
                              void* d_out, int out_size)
{
    const float* x  = (const float*)d_in[0];
    // d_in[1] = mask (int32 causal tril) — causality applied analytically
    const float* Wq = (const float*)d_in[2];
    const float* bq = (const float*)d_in[3];
    const float* Wk = (const float*)d_in[4];
    const float* bk = (const float*)d_in[5];
    const float* Wv = (const float*)d_in[6];
    const float* bv = (const float*)d_in[7];
    const float* Wo = (const float*)d_in[8];
    const float* bo = (const float*)d_in[9];
    float* out = (float*)d_out;

    // Host-side, idempotent, capture-legal (not a stream op, no allocation)
    cudaFuncSetAttribute(attn_mma_kernel,
                         cudaFuncAttributeMaxDynamicSharedMemorySize, ATTN_SMEM);

    // Q/K/V projections — separate launches (merged version measured slower)
    dim3 tgrid(DMODEL/128, MROWS/128);        // (8, 32)
    mma_gemm_qkv<<<tgrid, 256>>>(x, Wq, bq, 0);
    mma_gemm_qkv<<<tgrid, 256>>>(x, Wk, bk, 1);
    mma_gemm_qkv<<<tgrid, 256>>>(x, Wv, bv, 2);

    // Attention (cp.async double-buffered, reverse-qt)
    dim3 agrid(SEQ/64, BATCH*NH);             // (32, 32)
    attn_mma_kernel<<<agrid, 128, ATTN_SMEM>>>();

    // Output projection
    mma_gemm_out<<<tgrid, 256>>>(Wo, bo, out);
}